// round 12
// baseline (speedup 1.0000x reference)
#include <cuda_runtime.h>
#include <math.h>

#define BATCH 8
#define FEAT 512
#define NUM 512
#define KK 32
#define NSPLIT 8
#define NBLK 444      // 3 x 148 SMs, all co-resident at occ 3
#define P1_UNITS 256  // phase-1 units: 8 b x 32 tiles of 16 n
#define P2_UNITS 512  // phase-2 units: 8 n-chunks x 8 f-tiles x 8 b
#define P3_UNITS 512  // phase-3 units: 8 b x 64 f-groups

typedef unsigned long long ull;

// 1/sqrt(512): global L2 scale is exact (512 unit-norm rows per half)
#define GSC 0.04419417382415922f

// ---------------- device scratch (static, allocation-free) ----------------
__device__ float g_a[BATCH * NUM * KK];               // a[b][n][k]
__device__ float g_axp[NSPLIT * BATCH * FEAT * KK];   // partial ax  [s][b][f][k]
__device__ float g_ax2p[NSPLIT * BATCH * FEAT * KK];  // partial ax2 [s][b][f][k]
__device__ float g_asumt[BATCH * KK * 32];            // asum partials [b][k][tile]
__device__ unsigned g_cnt = 0;                        // barrier counter (self-resets)
__device__ unsigned g_gen = 0;                        // barrier generation (monotonic)
__device__ unsigned g_w1 = 0;                         // phase-1 work counter
__device__ unsigned g_w2 = 0;                         // phase-2 work counter

__device__ __forceinline__ float wsum(float v) {
#pragma unroll
    for (int o = 16; o; o >>= 1) v += __shfl_xor_sync(0xffffffffu, v, o);
    return v;
}
__device__ __forceinline__ float wmax(float v) {
#pragma unroll
    for (int o = 16; o; o >>= 1) v = fmaxf(v, __shfl_xor_sync(0xffffffffu, v, o));
    return v;
}

// packed f32x2 helpers (sm_100+)
__device__ __forceinline__ ull pk(float lo, float hi) {
    ull r;
    asm("mov.b64 %0, {%1, %2};" : "=l"(r) : "f"(lo), "f"(hi));
    return r;
}
__device__ __forceinline__ void upk(float& lo, float& hi, ull v) {
    asm("mov.b64 {%0, %1}, %2;" : "=f"(lo), "=f"(hi) : "l"(v));
}
__device__ __forceinline__ void ffma2(ull& d, ull a, ull b) {
    asm("fma.rn.f32x2 %0, %1, %2, %0;" : "+l"(d) : "l"(a), "l"(b));
}
__device__ __forceinline__ ull fmul2(ull a, ull b) {
    ull r;
    asm("mul.rn.f32x2 %0, %1, %2;" : "=l"(r) : "l"(a), "l"(b));
    return r;
}

// Replay-safe grid barrier. The releasing CTA optionally zeroes a work
// counter for the NEXT replay (all grabs from it are already done).
__device__ __forceinline__ void gridbar(unsigned* reset_ctr) {
    __syncthreads();
    if (threadIdx.x == 0) {
        __threadfence();
        unsigned gen = *((volatile unsigned*)&g_gen);
        if (atomicAdd(&g_cnt, 1u) == NBLK - 1u) {
            *((volatile unsigned*)&g_cnt) = 0u;
            if (reset_ctr) *((volatile unsigned*)reset_ctr) = 0u;
            __threadfence();
            atomicAdd(&g_gen, 1u);
        } else {
            while (*((volatile unsigned*)&g_gen) == gen) __nanosleep(64);
        }
        __threadfence();
    }
    __syncthreads();
}

// shared-memory phase union (~42.2KB; 3 CTAs/SM -> 127KB of 228KB)
struct P1 {
    float X4[128 * 16];        // [f][n16]; 16B rows -> LDS128 broadcast     (8KB)
    float W_s[32 * 129];       // [k][128f+pad]; lane=k stride 129 cf      (16.1KB)
    float red_f[8 * 32 * 17];  // f-partial logits [warp][lane][16n+pad]    (17KB)
    float asr[8 * 33];         // asum cross-warp                            (1KB)
};
struct P2 {
    float A_s[64 * 32];        // a half-tile [n][k]; LDS128 broadcast       (8KB)
    float Xs[64 * 64];         // x half-tile, XOR-swizzled                 (16KB)
};
union SMU {
    P1 p1;
    P2 p2;
};

// ---------------- single kernel: softmax -> bar -> gemm -> bar -> fv ---------
__global__ __launch_bounds__(256, 3) void k_all(const float* __restrict__ x,
                                                const float* __restrict__ W,
                                                const float* __restrict__ bias,
                                                const float* __restrict__ mu,
                                                const float* __restrict__ sigma,
                                                float* __restrict__ out) {
    __shared__ __align__(16) SMU sm;
    __shared__ int s_unit;
    const int tid  = threadIdx.x;
    const int w    = tid >> 5;
    const int lane = tid & 31;
    const int bx   = blockIdx.x;

    // ================= PHASE 1 (dynamic): logits + softmax + asum ============
    // unit u: b = u>>5, 16-n tile = u&31. Warps split f; 8 f32x2 acc chains.
    for (;;) {
        __syncthreads();
        if (tid == 0) s_unit = (int)atomicAdd(&g_w1, 1u);
        __syncthreads();
        const int u = s_unit;
        if (u >= P1_UNITS) break;
        const int b  = u >> 5;
        const int n0 = (u & 31) * 16;

        ull acc[8] = {0, 0, 0, 0, 0, 0, 0, 0};

        for (int t = 0; t < 4; t++) {
            const int fb = t * 128;
            __syncthreads();
            // stage W chunk [32 k][128 f] (stride-129 rows, cf stores)
#pragma unroll
            for (int i = 0; i < 16; i++) {
                int idx = tid + i * 256;
                int k = idx >> 7, fl = idx & 127;
                sm.p1.W_s[k * 129 + fl] = W[k * FEAT + fb + fl];
            }
            // stage X chunk [128 f][16 n]: float4 + STS.128 (cf)
#pragma unroll
            for (int i = 0; i < 2; i++) {
                int idx = tid + i * 256;
                int fr = idx >> 2, c4 = (idx & 3) * 4;
                float4 v = *reinterpret_cast<const float4*>(
                    &x[((size_t)b * FEAT + fb + fr) * NUM + n0 + c4]);
                *reinterpret_cast<float4*>(&sm.p1.X4[fr * 16 + c4]) = v;
            }
            __syncthreads();
            const int fw = w * 16;
#pragma unroll 4
            for (int fi = 0; fi < 16; fi++) {
                const int fl = fw + fi;
                float wv = sm.p1.W_s[lane * 129 + fl];           // LDS32 cf
                ull   wp = pk(wv, wv);
                const ulonglong2* xr = reinterpret_cast<const ulonglong2*>(&sm.p1.X4[fl * 16]);
                ulonglong2 xa = xr[0];                            // LDS128 bc
                ulonglong2 xb = xr[1];
                ffma2(acc[0], wp, xa.x);
                ffma2(acc[1], wp, xa.y);
                ffma2(acc[2], wp, xb.x);
                ffma2(acc[3], wp, xb.y);
                xa = xr[2];
                xb = xr[3];
                ffma2(acc[4], wp, xa.x);
                ffma2(acc[5], wp, xa.y);
                ffma2(acc[6], wp, xb.x);
                ffma2(acc[7], wp, xb.y);
            }
        }

        // f-partials: red_f[w][lane][16n], lane stride 17 -> conflict-free
        __syncthreads();
        {
            float* r = &sm.p1.red_f[(w * 32 + lane) * 17];
#pragma unroll
            for (int j = 0; j < 8; j++) {
                float f0, f1;
                upk(f0, f1, acc[j]);
                r[2 * j]     = f0;
                r[2 * j + 1] = f1;
            }
        }
        __syncthreads();

        // warp p combines f-partials for n-pair p, softmaxes its 2 n's
        {
            float l0 = 0.f, l1 = 0.f;
#pragma unroll
            for (int g = 0; g < 8; g++) {
                const float* r = &sm.p1.red_f[(g * 32 + lane) * 17 + 2 * w];
                l0 += r[0];
                l1 += r[1];
            }
            const float bv = bias[lane];
            float pa;
            {
                float lg = l0 + bv;
                float m = wmax(lg);
                float e = __expf(lg - m);
                float s = wsum(e);
                float a = e / s;
                g_a[((size_t)b * NUM + n0 + 2 * w) * KK + lane] = a;
                pa = a;
            }
            {
                float lg = l1 + bv;
                float m = wmax(lg);
                float e = __expf(lg - m);
                float s = wsum(e);
                float a = e / s;
                g_a[((size_t)b * NUM + n0 + 2 * w + 1) * KK + lane] = a;
                pa += a;
            }
            sm.p1.asr[w * 33 + lane] = pa;
        }
        __syncthreads();
        if (tid < 32) {
            float s = 0.f;
#pragma unroll
            for (int g = 0; g < 8; g++) s += sm.p1.asr[g * 33 + tid];
            g_asumt[((size_t)b * KK + tid) * 32 + (u & 31)] = s;
        }
    }

    gridbar(&g_w1);   // releaser re-zeros phase-1 counter for next replay

    // ================= PHASE 2 (dynamic): ax / ax2 GEMM partials ==============
    // unit u: n-chunk c = u&7, f-tile ft = (u>>3)&7, b = u>>6.
    // warp = 4 k-groups x 2 f-halves; thread = 1 f x 8 k (8 ull accs).
    {
        const int kg = w & 3;
        const int fh = w >> 2;
        const int kbase = kg * 8;
        const int flo = fh * 32 + lane;

        for (;;) {
            __syncthreads();
            if (tid == 0) s_unit = (int)atomicAdd(&g_w2, 1u);
            __syncthreads();
            const int u = s_unit;
            if (u >= P2_UNITS) break;
            const int c  = u & 7;
            const int ft = (u >> 3) & 7;
            const int b  = u >> 6;
            const int f0 = ft * 64;
            const int n0 = c * 64;

            // stage A half-tile [64 n][32 k]
#pragma unroll
            for (int i = 0; i < 2; i++) {
                int idx = tid + i * 256;
                int nl = idx >> 3, kq = (idx & 7) * 4;
                float4 v = *reinterpret_cast<const float4*>(
                    &g_a[((size_t)b * NUM + n0 + nl) * KK + kq]);
                *reinterpret_cast<float4*>(&sm.p2.A_s[nl * 32 + kq]) = v;
            }
            // stage X half-tile [64 f][64 n], XOR-swizzled
            {
                const int sr = w * 8;
#pragma unroll
                for (int r = 0; r < 8; r++) {
                    const int fr = sr + r;
                    const int sw = fr & 31;
                    const float* src = &x[((size_t)b * FEAT + f0 + fr) * NUM + n0];
                    float* dst = &sm.p2.Xs[fr * 64];
#pragma unroll
                    for (int cc = 0; cc < 2; cc++) {
                        int nc = cc * 32 + lane;
                        dst[nc ^ sw] = src[nc];
                    }
                }
            }
            __syncthreads();

            ull a1[4] = {0, 0, 0, 0}, a2[4] = {0, 0, 0, 0};
            const float* xrow = &sm.p2.Xs[flo * 64];
#pragma unroll 8
            for (int nl = 0; nl < 64; nl++) {
                float xv = xrow[nl ^ lane];          // LDS32 cf
                ull xp = pk(xv, xv);
                ull x2 = fmul2(xp, xp);
                const float* arow = &sm.p2.A_s[nl * 32 + kbase];
                ulonglong2 a01 = *reinterpret_cast<const ulonglong2*>(arow);      // LDS128 bc
                ulonglong2 a23 = *reinterpret_cast<const ulonglong2*>(arow + 4);  // LDS128 bc
                ffma2(a1[0], a01.x, xp);  ffma2(a2[0], a01.x, x2);
                ffma2(a1[1], a01.y, xp);  ffma2(a2[1], a01.y, x2);
                ffma2(a1[2], a23.x, xp);  ffma2(a2[2], a23.x, x2);
                ffma2(a1[3], a23.y, xp);  ffma2(a2[3], a23.y, x2);
            }

            const size_t base = (((size_t)c * BATCH + b) * FEAT + f0 + flo) * KK + kbase;
            *reinterpret_cast<ulonglong2*>(&g_axp[base])      = make_ulonglong2(a1[0], a1[1]);
            *reinterpret_cast<ulonglong2*>(&g_axp[base + 4])  = make_ulonglong2(a1[2], a1[3]);
            *reinterpret_cast<ulonglong2*>(&g_ax2p[base])     = make_ulonglong2(a2[0], a2[1]);
            *reinterpret_cast<ulonglong2*>(&g_ax2p[base + 4]) = make_ulonglong2(a2[2], a2[3]);
        }
    }

    gridbar(&g_w2);   // releaser re-zeros phase-2 counter for next replay

    // ================= PHASE 3: fisher vectors + rownorm + const scale ========
    // 512 units strided over 444 CTAs: u -> b = u>>6, fg = u&63, f = fg*8 + w.
    for (int u = bx; u < P3_UNITS; u += NBLK) {
        const int b  = u >> 6;
        const int fg = u & 63;
        const int f  = fg * 8 + w;

        // asum[b][k]: 32 contiguous partials -> 8x LDG.128
        float asv = 0.f;
        {
            const float4* p = reinterpret_cast<const float4*>(&g_asumt[((size_t)b * KK + lane) * 32]);
#pragma unroll
            for (int q = 0; q < 8; q++) {
                float4 v = p[q];
                asv += (v.x + v.y) + (v.z + v.w);
            }
        }

        float ax = 0.f, ax2 = 0.f;
#pragma unroll
        for (int s = 0; s < NSPLIT; s++) {
            size_t po = (((size_t)s * BATCH + b) * FEAT + f) * KK + lane;
            ax  += g_axp[po];
            ax2 += g_ax2p[po];
        }
        float muv = mu[f * KK + lane];
        float sg  = sigma[f * KK + lane];
        float fv1 = (ax - muv * asv) / sg;
        float fv2 = (ax2 - 2.f * muv * ax + muv * muv * asv) / (sg * sg) - asv;

        float n1 = sqrtf(wsum(fv1 * fv1));
        float n2 = sqrtf(wsum(fv2 * fv2));
        float v1 = fv1 / fmaxf(n1, 1e-12f) * GSC;
        float v2 = fv2 / fmaxf(n2, 1e-12f) * GSC;

        const size_t ob = (size_t)b * 2 * FEAT * KK;
        out[ob + (size_t)f * KK + lane]             = v1;
        out[ob + FEAT * KK + (size_t)f * KK + lane] = v2;
    }
}

// ---------------- launch -----------------------------------------------------
extern "C" void kernel_launch(void* const* d_in, const int* in_sizes, int n_in,
                              void* d_out, int out_size) {
    (void)in_sizes; (void)n_in; (void)out_size;
    const float* x     = (const float*)d_in[0];
    const float* W     = (const float*)d_in[1];
    const float* bias  = (const float*)d_in[2];
    const float* mu    = (const float*)d_in[3];
    const float* sigma = (const float*)d_in[4];
    float* out = (float*)d_out;

    k_all<<<NBLK, 256>>>(x, W, bias, mu, sigma, out);
}

// round 13
// speedup vs baseline: 1.2604x; 1.2604x over previous
#include <cuda_runtime.h>
#include <math.h>

#define BATCH 8
#define FEAT 512
#define NUM 512
#define KK 32
#define NSPLIT 16
#define NBLK 296      // 2 x 148 SMs
#define P2_UNITS 512  // 8 n-chunks x 8 f-tiles x 8 batches

typedef unsigned long long ull;

// 1/sqrt(512): global L2 scale is exact (512 unit-norm rows per half)
#define GSC 0.04419417382415922f

// ---------------- device scratch (static, allocation-free) ----------------
__device__ float g_a[BATCH * NUM * KK];               // a[b][n][k]
__device__ float g_axp[NSPLIT * BATCH * FEAT * KK];   // partial ax  [s][b][f][k]
__device__ float g_ax2p[NSPLIT * BATCH * FEAT * KK];  // partial ax2 [s][b][f][k]
__device__ float g_asumt[BATCH * KK * 32];            // asum partials [b][k][tile]
__device__ unsigned g_cnt = 0;                        // barrier counter (self-resets)
__device__ unsigned g_gen = 0;                        // barrier generation (monotonic)
__device__ unsigned g_work = 0;                       // phase-2 dynamic unit counter

__device__ __forceinline__ float wsum(float v) {
#pragma unroll
    for (int o = 16; o; o >>= 1) v += __shfl_xor_sync(0xffffffffu, v, o);
    return v;
}
__device__ __forceinline__ float wmax(float v) {
#pragma unroll
    for (int o = 16; o; o >>= 1) v = fmaxf(v, __shfl_xor_sync(0xffffffffu, v, o));
    return v;
}

// packed f32x2 helpers (sm_100+)
__device__ __forceinline__ ull pk(float lo, float hi) {
    ull r;
    asm("mov.b64 %0, {%1, %2};" : "=l"(r) : "f"(lo), "f"(hi));
    return r;
}
__device__ __forceinline__ void upk(float& lo, float& hi, ull v) {
    asm("mov.b64 {%0, %1}, %2;" : "=f"(lo), "=f"(hi) : "l"(v));
}
__device__ __forceinline__ void ffma2(ull& d, ull a, ull b) {
    asm("fma.rn.f32x2 %0, %1, %2, %0;" : "+l"(d) : "l"(a), "l"(b));
}
__device__ __forceinline__ ull fmul2(ull a, ull b) {
    ull r;
    asm("mul.rn.f32x2 %0, %1, %2;" : "=l"(r) : "l"(a), "l"(b));
    return r;
}
__device__ __forceinline__ float fold(ull v) {
    float lo, hi;
    upk(lo, hi, v);
    return lo + hi;
}

// Replay-safe grid barrier (volatile-load polling, monotonic generation).
__device__ __forceinline__ void gridbar() {
    __syncthreads();
    if (threadIdx.x == 0) {
        __threadfence();
        unsigned gen = *((volatile unsigned*)&g_gen);
        if (atomicAdd(&g_cnt, 1u) == NBLK - 1u) {
            *((volatile unsigned*)&g_cnt) = 0u;
            __threadfence();
            atomicAdd(&g_gen, 1u);
        } else {
            while (*((volatile unsigned*)&g_gen) == gen) __nanosleep(64);
        }
        __threadfence();
    }
    __syncthreads();
}

// shared-memory phase union
struct P1 {
    float X4[128 * 16];        // [f][n16]; 16B rows -> LDS128 broadcast     (8KB)
    float W_s[32 * 129];       // [k][128f+pad]; lane=k stride 129 cf      (16.1KB)
    float red_f[8 * 32 * 17];  // f-partial logits [warp][lane][16n+pad]    (17KB)
    float asr[8 * 33];         // asum cross-warp                            (1KB)
};
struct P2 {
    ull At[32 * 33];           // a TRANSPOSED [k][n-pair]; stride 33 (odd)  (8.4KB)
    ull Xs[64 * 34];           // x [f][n-pair]; stride 34 (16B-align f4)   (17.4KB)
};
union SMU {
    P1 p1;
    P2 p2;
};

// ---------------- single kernel: softmax -> bar -> gemm -> bar -> fv ---------
__global__ __launch_bounds__(256, 2) void k_all(const float* __restrict__ x,
                                                const float* __restrict__ W,
                                                const float* __restrict__ bias,
                                                const float* __restrict__ mu,
                                                const float* __restrict__ sigma,
                                                float* __restrict__ out) {
    __shared__ __align__(16) SMU sm;
    __shared__ int s_unit;
    const int tid  = threadIdx.x;
    const int w    = tid >> 5;
    const int lane = tid & 31;
    const int bx   = blockIdx.x;

    // reset phase-2 work counter for this replay (ordered before use by gridbar)
    if (bx == 0 && tid == 0) *((volatile unsigned*)&g_work) = 0u;

    // ================= PHASE 1: logits + softmax + asum (r11 verbatim) =======
    if (bx < 256) {
        const int b    = bx >> 5;
        const int tile = bx & 31;
        const int n0   = tile * 16;

        ull acc[8] = {0, 0, 0, 0, 0, 0, 0, 0};

        for (int t = 0; t < 4; t++) {
            const int fb = t * 128;
            __syncthreads();
#pragma unroll
            for (int i = 0; i < 16; i++) {
                int idx = tid + i * 256;
                int k = idx >> 7, fl = idx & 127;
                sm.p1.W_s[k * 129 + fl] = W[k * FEAT + fb + fl];
            }
#pragma unroll
            for (int i = 0; i < 2; i++) {
                int idx = tid + i * 256;
                int fr = idx >> 2, c4 = (idx & 3) * 4;
                float4 v = *reinterpret_cast<const float4*>(
                    &x[((size_t)b * FEAT + fb + fr) * NUM + n0 + c4]);
                *reinterpret_cast<float4*>(&sm.p1.X4[fr * 16 + c4]) = v;
            }
            __syncthreads();
            const int fw = w * 16;
#pragma unroll 4
            for (int fi = 0; fi < 16; fi++) {
                const int fl = fw + fi;
                float wv = sm.p1.W_s[lane * 129 + fl];           // LDS32 cf
                ull   wp = pk(wv, wv);
                const ulonglong2* xr = reinterpret_cast<const ulonglong2*>(&sm.p1.X4[fl * 16]);
                ulonglong2 xa = xr[0];                            // LDS128 bc
                ulonglong2 xb = xr[1];
                ffma2(acc[0], wp, xa.x);
                ffma2(acc[1], wp, xa.y);
                ffma2(acc[2], wp, xb.x);
                ffma2(acc[3], wp, xb.y);
                xa = xr[2];
                xb = xr[3];
                ffma2(acc[4], wp, xa.x);
                ffma2(acc[5], wp, xa.y);
                ffma2(acc[6], wp, xb.x);
                ffma2(acc[7], wp, xb.y);
            }
        }

        __syncthreads();
        {
            float* r = &sm.p1.red_f[(w * 32 + lane) * 17];
#pragma unroll
            for (int j = 0; j < 8; j++) {
                float f0, f1;
                upk(f0, f1, acc[j]);
                r[2 * j]     = f0;
                r[2 * j + 1] = f1;
            }
        }
        __syncthreads();

        {
            float l0 = 0.f, l1 = 0.f;
#pragma unroll
            for (int g = 0; g < 8; g++) {
                const float* r = &sm.p1.red_f[(g * 32 + lane) * 17 + 2 * w];
                l0 += r[0];
                l1 += r[1];
            }
            const float bv = bias[lane];
            float pa;
            {
                float lg = l0 + bv;
                float m = wmax(lg);
                float e = __expf(lg - m);
                float s = wsum(e);
                float a = e / s;
                g_a[((size_t)b * NUM + n0 + 2 * w) * KK + lane] = a;
                pa = a;
            }
            {
                float lg = l1 + bv;
                float m = wmax(lg);
                float e = __expf(lg - m);
                float s = wsum(e);
                float a = e / s;
                g_a[((size_t)b * NUM + n0 + 2 * w + 1) * KK + lane] = a;
                pa += a;
            }
            sm.p1.asr[w * 33 + lane] = pa;
        }
        __syncthreads();
        if (tid < 32) {
            float s = 0.f;
#pragma unroll
            for (int g = 0; g < 8; g++) s += sm.p1.asr[g * 33 + tid];
            g_asumt[((size_t)b * KK + tid) * 32 + tile] = s;
        }
    }

    gridbar();

    // ================= PHASE 2 (dynamic): square-tiled GEMM, n-pair packed ====
    // unit u: n-chunk c = u&7 (64 n), f-tile ft = (u>>3)&7 (64 f), b = u>>6.
    // warps: fh = w&1 (32 f), kh = (w>>1)&1 (16 k), nq = w>>2 (32 n).
    // lanes: fg = lane>>2 (8), kg = lane&3 (4). thread = 4f x 4k x n-pairs.
    {
        const int fh = w & 1;
        const int kh = (w >> 1) & 1;
        const int nq = w >> 2;
        const int fgl = (fh << 5) + (lane >> 2);   // f local base (j adds 8)
        const int kbase = (kh << 4) + (lane & 3) * 4;

        for (;;) {
            __syncthreads();               // prior unit fully consumed
            if (tid == 0) s_unit = (int)atomicAdd(&g_work, 1u);
            __syncthreads();
            const int u = s_unit;
            if (u >= P2_UNITS) break;
            const int c  = u & 7;
            const int ft = (u >> 3) & 7;
            const int b  = u >> 6;
            const int f0 = ft * 64;
            const int n0 = c * 64;

            // stage A TRANSPOSED: At[k][n] (float view stride 66), 2 float4/thread
            float* Atf = reinterpret_cast<float*>(sm.p2.At);
#pragma unroll
            for (int i = 0; i < 2; i++) {
                int idx = tid + i * 256;
                int nl = idx >> 3, kq = (idx & 7) * 4;
                float4 v = *reinterpret_cast<const float4*>(
                    &g_a[((size_t)b * NUM + n0 + nl) * KK + kq]);
                Atf[(kq + 0) * 66 + nl] = v.x;
                Atf[(kq + 1) * 66 + nl] = v.y;
                Atf[(kq + 2) * 66 + nl] = v.z;
                Atf[(kq + 3) * 66 + nl] = v.w;
            }
            // stage X rows [64 f][64 n] (float view stride 68), 4 float4/thread
            float* Xsf = reinterpret_cast<float*>(sm.p2.Xs);
#pragma unroll
            for (int i = 0; i < 4; i++) {
                int idx = tid + i * 256;
                int fr = idx >> 4, nc = (idx & 15) * 4;
                float4 v = *reinterpret_cast<const float4*>(
                    &x[((size_t)b * FEAT + f0 + fr) * NUM + n0 + nc]);
                *reinterpret_cast<float4*>(&Xsf[fr * 68 + nc]) = v;
            }
            __syncthreads();

            ull ac1[4][4], ac2[4][4];
#pragma unroll
            for (int j = 0; j < 4; j++)
#pragma unroll
                for (int m = 0; m < 4; m++) { ac1[j][m] = 0ULL; ac2[j][m] = 0ULL; }

            const ull* Xrow = &sm.p2.Xs[(size_t)fgl * 34 + nq * 16];
            const ull* Arow = &sm.p2.At[(size_t)kbase * 33 + nq * 16];

#pragma unroll 4
            for (int np = 0; np < 16; np++) {
                ull x0 = Xrow[np];             // LDS64, fg-distinct (stride 34 -> cf)
                ull x1 = Xrow[np + 8 * 34];
                ull x2 = Xrow[np + 16 * 34];
                ull x3 = Xrow[np + 24 * 34];
                ull a0 = Arow[np];             // LDS64, kg-distinct quad rows (cf)
                ull a1 = Arow[np + 33];
                ull a2 = Arow[np + 66];
                ull a3 = Arow[np + 99];
                ull q0 = fmul2(x0, x0);
                ull q1 = fmul2(x1, x1);
                ull q2 = fmul2(x2, x2);
                ull q3 = fmul2(x3, x3);
                ffma2(ac1[0][0], a0, x0);  ffma2(ac2[0][0], a0, q0);
                ffma2(ac1[0][1], a1, x0);  ffma2(ac2[0][1], a1, q0);
                ffma2(ac1[0][2], a2, x0);  ffma2(ac2[0][2], a2, q0);
                ffma2(ac1[0][3], a3, x0);  ffma2(ac2[0][3], a3, q0);
                ffma2(ac1[1][0], a0, x1);  ffma2(ac2[1][0], a0, q1);
                ffma2(ac1[1][1], a1, x1);  ffma2(ac2[1][1], a1, q1);
                ffma2(ac1[1][2], a2, x1);  ffma2(ac2[1][2], a2, q1);
                ffma2(ac1[1][3], a3, x1);  ffma2(ac2[1][3], a3, q1);
                ffma2(ac1[2][0], a0, x2);  ffma2(ac2[2][0], a0, q2);
                ffma2(ac1[2][1], a1, x2);  ffma2(ac2[2][1], a1, q2);
                ffma2(ac1[2][2], a2, x2);  ffma2(ac2[2][2], a2, q2);
                ffma2(ac1[2][3], a3, x2);  ffma2(ac2[2][3], a3, q2);
                ffma2(ac1[3][0], a0, x3);  ffma2(ac2[3][0], a0, q3);
                ffma2(ac1[3][1], a1, x3);  ffma2(ac2[3][1], a1, q3);
                ffma2(ac1[3][2], a2, x3);  ffma2(ac2[3][2], a2, q3);
                ffma2(ac1[3][3], a3, x3);  ffma2(ac2[3][3], a3, q3);
            }

            // fold even/odd n partials, store float4 per (f, ax/ax2)
            const int split = c * 2 + nq;
#pragma unroll
            for (int j = 0; j < 4; j++) {
                const int f = f0 + fgl + 8 * j;
                const size_t base =
                    (((size_t)split * BATCH + b) * FEAT + f) * KK + kbase;
                float4 v1, v2;
                v1.x = fold(ac1[j][0]); v1.y = fold(ac1[j][1]);
                v1.z = fold(ac1[j][2]); v1.w = fold(ac1[j][3]);
                v2.x = fold(ac2[j][0]); v2.y = fold(ac2[j][1]);
                v2.z = fold(ac2[j][2]); v2.w = fold(ac2[j][3]);
                *reinterpret_cast<float4*>(&g_axp[base])  = v1;
                *reinterpret_cast<float4*>(&g_ax2p[base]) = v2;
            }
        }
    }

    gridbar();

    // ================= PHASE 3: fisher vectors + rownorm + const scale ========
    if (bx < 256) {
        const int b      = bx >> 5;
        const int fgbase = (bx & 31) * 2;

        // asum[b][k]: 32 contiguous partials -> 8x LDG.128
        float asv = 0.f;
        {
            const float4* p = reinterpret_cast<const float4*>(&g_asumt[((size_t)b * KK + lane) * 32]);
#pragma unroll
            for (int q = 0; q < 8; q++) {
                float4 v = p[q];
                asv += (v.x + v.y) + (v.z + v.w);
            }
        }

#pragma unroll
        for (int j = 0; j < 2; j++) {
            const int f = (fgbase + j) * 8 + w;
            float ax = 0.f, ax2 = 0.f;
#pragma unroll
            for (int s = 0; s < NSPLIT; s++) {
                size_t po = (((size_t)s * BATCH + b) * FEAT + f) * KK + lane;
                ax  += g_axp[po];
                ax2 += g_ax2p[po];
            }
            float muv = mu[f * KK + lane];
            float sg  = sigma[f * KK + lane];
            float fv1 = (ax - muv * asv) / sg;
            float fv2 = (ax2 - 2.f * muv * ax + muv * muv * asv) / (sg * sg) - asv;

            float n1 = sqrtf(wsum(fv1 * fv1));
            float n2 = sqrtf(wsum(fv2 * fv2));
            float v1 = fv1 / fmaxf(n1, 1e-12f) * GSC;
            float v2 = fv2 / fmaxf(n2, 1e-12f) * GSC;

            const size_t ob = (size_t)b * 2 * FEAT * KK;
            out[ob + (size_t)f * KK + lane]             = v1;
            out[ob + FEAT * KK + (size_t)f * KK + lane] = v2;
        }
    }
}

// ---------------- launch -----------------------------------------------------
extern "C" void kernel_launch(void* const* d_in, const int* in_sizes, int n_in,
                              void* d_out, int out_size) {
    (void)in_sizes; (void)n_in; (void)out_size;
    const float* x     = (const float*)d_in[0];
    const float* W     = (const float*)d_in[1];
    const float* bias  = (const float*)d_in[2];
    const float* mu    = (const float*)d_in[3];
    const float* sigma = (const float*)d_in[4];
    float* out = (float*)d_out;

    k_all<<<NBLK, 256>>>(x, W, bias, mu, sigma, out);
}